// round 12
// baseline (speedup 1.0000x reference)
#include <cuda_runtime.h>
#include <cuda_fp16.h>
#include <cstdint>

// Causal attention B=2,H=16,S=2048,D=64 fp32. fp16 mma.sync m16n8k16.
// R12: deferred MMA2 — iteration kt issues MMA2(kt-1)+MMA1(kt) as one dense
// HMMA block; softmax(kt) results consumed next iter (ex2 latency hidden by
// the barrier). Triple-buffered smem so V(kt-1) survives prefetch(kt+1).

#define S_LEN 2048
#define DH    64
#define BR    128
#define BC    64
#define NT    128
#define NQT   (S_LEN/BR)                 // 16
#define BH_N  32
#define NJOBS (NQT*BH_N)                 // 512
#define NCTA  296                        // 2 per SM
#define KPAD  72
#define ROWB  (KPAD*2)                   // 144 B per smem row
#define BUFB  (BC*ROWB)                  // 9216 B per K (or V) buffer
#define NBUF  3
#define SMEM_BYTES (NBUF*BUFB*2)         // 55296
#define SC_LOG2E 0.1803368801111204f     // (1/8)*log2(e)
#define NEGINF __int_as_float(0xff800000)

#define KV_ELEMS ((size_t)BH_N * S_LEN * DH)
__device__ __align__(16) __half g_Kh[KV_ELEMS];
__device__ __align__(16) __half g_Vh[KV_ELEMS];
__device__ int g_job;

__device__ __forceinline__ uint32_t smem_u32(const void* p){
    uint32_t a;
    asm("{ .reg .u64 t; cvta.to.shared.u64 t, %1; cvt.u32.u64 %0, t; }" : "=r"(a) : "l"(p));
    return a;
}
__device__ __forceinline__ uint32_t h2(float a, float b){
    __half2 v = __floats2half2_rn(a, b);
    return *reinterpret_cast<uint32_t*>(&v);
}
__device__ __forceinline__ uint32_t ex2h2(uint32_t x){
    uint32_t y; asm("ex2.approx.f16x2 %0, %1;" : "=r"(y) : "r"(x)); return y;
}
__device__ __forceinline__ void ldm_x4(uint32_t r[4], uint32_t addr){
    asm volatile("ldmatrix.sync.aligned.m8n8.x4.shared.b16 {%0,%1,%2,%3}, [%4];"
                 : "=r"(r[0]), "=r"(r[1]), "=r"(r[2]), "=r"(r[3]) : "r"(addr));
}
__device__ __forceinline__ void ldm_x4_t(uint32_t r[4], uint32_t addr){
    asm volatile("ldmatrix.sync.aligned.m8n8.x4.trans.shared.b16 {%0,%1,%2,%3}, [%4];"
                 : "=r"(r[0]), "=r"(r[1]), "=r"(r[2]), "=r"(r[3]) : "r"(addr));
}
__device__ __forceinline__ void mma_f16(float d[4], const uint32_t a[4],
                                        const uint32_t b[2]){
    asm volatile(
        "mma.sync.aligned.m16n8k16.row.col.f32.f16.f16.f32 "
        "{%0,%1,%2,%3}, {%4,%5,%6,%7}, {%8,%9}, {%0,%1,%2,%3};"
        : "+f"(d[0]), "+f"(d[1]), "+f"(d[2]), "+f"(d[3])
        : "r"(a[0]), "r"(a[1]), "r"(a[2]), "r"(a[3]),
          "r"(b[0]), "r"(b[1]));
}
__device__ __forceinline__ void cp16(uint32_t dst, const void* src){
    asm volatile("cp.async.cg.shared.global [%0], [%1], 16;" :: "r"(dst), "l"(src));
}
#define CP_COMMIT() asm volatile("cp.async.commit_group;")
#define CP_WAIT0()  asm volatile("cp.async.wait_group 0;")

__global__ void __launch_bounds__(256) convKV(const float* __restrict__ K,
                                              const float* __restrict__ V){
    if (blockIdx.x == 0 && threadIdx.x == 0) g_job = 0;
    size_t i = ((size_t)blockIdx.x * 256 + threadIdx.x) * 4;
    float4 k = *reinterpret_cast<const float4*>(K + i);
    float4 v = *reinterpret_cast<const float4*>(V + i);
    uint2 ku; ku.x = h2(k.x, k.y); ku.y = h2(k.z, k.w);
    uint2 vu; vu.x = h2(v.x, v.y); vu.y = h2(v.z, v.w);
    *reinterpret_cast<uint2*>(&g_Kh[i]) = ku;
    *reinterpret_cast<uint2*>(&g_Vh[i]) = vu;
}

// MMA2 over full 64-K with P fragments (4 indep chains per nb-pair + sums)
__device__ __forceinline__ void do_mma2(
    float o0[9][4], float o1[9][4],
    const uint32_t apA0[8], const uint32_t apA1[8],
    const uint32_t apB0[8], const uint32_t apB1[8],
    uint32_t vb /*buffer base*/, uint32_t vmoff, const uint32_t bsum[2])
{
    #pragma unroll
    for (int np = 0; np < 4; np++) {
        uint32_t bv0[8], bv1[8];
        uint32_t a0 = vb + vmoff + (uint32_t)((2 * np) * 16);
        ldm_x4_t(bv0,     a0);
        ldm_x4_t(bv0 + 4, a0 + 32 * ROWB);
        ldm_x4_t(bv1,     a0 + 16);
        ldm_x4_t(bv1 + 4, a0 + 16 + 32 * ROWB);
        #pragma unroll
        for (int kb = 0; kb < 4; kb++) {
            uint32_t A0[4] = {apA0[2*kb], apA1[2*kb], apA0[2*kb+1], apA1[2*kb+1]};
            uint32_t A1[4] = {apB0[2*kb], apB1[2*kb], apB0[2*kb+1], apB1[2*kb+1]};
            mma_f16(o0[2*np],     A0, bv0 + 2*kb);
            mma_f16(o1[2*np],     A1, bv0 + 2*kb);
            mma_f16(o0[2*np + 1], A0, bv1 + 2*kb);
            mma_f16(o1[2*np + 1], A1, bv1 + 2*kb);
        }
    }
    #pragma unroll
    for (int kb = 0; kb < 4; kb++) {
        uint32_t A0[4] = {apA0[2*kb], apA1[2*kb], apA0[2*kb+1], apA1[2*kb+1]};
        uint32_t A1[4] = {apB0[2*kb], apB1[2*kb], apB0[2*kb+1], apB1[2*kb+1]};
        mma_f16(o0[8], A0, bsum);
        mma_f16(o1[8], A1, bsum);
    }
}

// MMA1 + softmax: produces next iteration's P fragments
__device__ __forceinline__ void do_mma1_softmax(
    const uint32_t aq[2][4][4],
    uint32_t apA0[8], uint32_t apA1[8], uint32_t apB0[8], uint32_t apB1[8],
    uint32_t ka /*ksb+kmoff*/, bool hasmask, int ktbase, int rA, int rB, int j2)
{
    #pragma unroll
    for (int ntp = 0; ntp < 4; ntp++) {
        const int nt0 = 2 * ntp;
        uint32_t b0[8], b1[8];
        uint32_t a0 = ka + (uint32_t)(nt0 * 8 * ROWB);
        ldm_x4(b0,     a0);
        ldm_x4(b0 + 4, a0 + 64);
        ldm_x4(b1,     a0 + 8 * ROWB);
        ldm_x4(b1 + 4, a0 + 8 * ROWB + 64);
        float sA0[4] = {0,0,0,0}, sB0[4] = {0,0,0,0};
        float sA1[4] = {0,0,0,0}, sB1[4] = {0,0,0,0};
        #pragma unroll
        for (int kb = 0; kb < 4; kb++) {
            mma_f16(sA0, aq[0][kb], b0 + 2*kb);
            mma_f16(sB0, aq[1][kb], b0 + 2*kb);
            mma_f16(sA1, aq[0][kb], b1 + 2*kb);
            mma_f16(sB1, aq[1][kb], b1 + 2*kb);
        }
        #pragma unroll
        for (int u = 0; u < 2; u++) {
            float* sA = u ? sA1 : sA0;
            float* sB = u ? sB1 : sB0;
            if (hasmask) {
                int c0 = ktbase + (nt0 + u) * 8 + j2;
                if (c0     > rA)     sA[0] = NEGINF;
                if (c0 + 1 > rA)     sA[1] = NEGINF;
                if (c0     > rA + 8) sA[2] = NEGINF;
                if (c0 + 1 > rA + 8) sA[3] = NEGINF;
                if (c0     > rB)     sB[0] = NEGINF;
                if (c0 + 1 > rB)     sB[1] = NEGINF;
                if (c0     > rB + 8) sB[2] = NEGINF;
                if (c0 + 1 > rB + 8) sB[3] = NEGINF;
            }
            apA0[nt0 + u] = ex2h2(h2(sA[0], sA[1]));
            apA1[nt0 + u] = ex2h2(h2(sA[2], sA[3]));
            apB0[nt0 + u] = ex2h2(h2(sB[0], sB[1]));
            apB1[nt0 + u] = ex2h2(h2(sB[2], sB[3]));
        }
    }
}

__global__ void __launch_bounds__(NT, 2) attn_f16(
    const float* __restrict__ Q, float* __restrict__ O)
{
    extern __shared__ __align__(16) __half sm[];
    __shared__ int sjob;

    const int t = threadIdx.x, lane = t & 31, w = t >> 5;
    const int g = lane >> 2, j = lane & 3;

    const uint32_t ks0 = smem_u32(sm);                       // K buffers 0..2
    const uint32_t vs0 = ks0 + NBUF * BUFB;                  // V buffers 0..2
    const uint32_t kmoff = (uint32_t)((lane & 7) * ROWB + (lane >> 3) * 16);
    const uint32_t vmoff = (uint32_t)(lane * ROWB);

    uint32_t kds[4], vds[4];
    int ld_e[4];
    #pragma unroll
    for (int i = 0; i < 4; i++) {
        int idx = t + i * NT;
        int row = idx >> 3, chb = (idx & 7) * 16;
        kds[i] = ks0 + (uint32_t)(row * ROWB + chb);
        vds[i] = vs0 + (uint32_t)(row * ROWB + chb);
        ld_e[i] = row * DH + (chb >> 1);
    }

    const uint32_t bones = (lane < 4) ? 0x3C003C00u : 0u;
    const uint32_t bsum[2] = {bones, bones};

    while (true) {
        if (t == 0) sjob = atomicAdd(&g_job, 1);
        __syncthreads();
        const int job = sjob;
        if (job >= NJOBS) break;
        const int q  = (NQT - 1) - (job >> 5);
        const int bh = job & 31;
        const int nkt = 2 * (q + 1);
        const size_t base = (size_t)bh * S_LEN * DH;
        const __half* Kh = g_Kh + base;
        const __half* Vh = g_Vh + base;
        const int rbase = q * BR + w * 32;
        const int last_w = (rbase + 31) >> 6;      // last kt with MMA1 work
        const int rA = rbase + g, rB = rA + 16, j2 = 2 * j;

        #pragma unroll
        for (int i = 0; i < 4; i++) {
            cp16(kds[i], Kh + ld_e[i]);
            cp16(vds[i], Vh + ld_e[i]);
        }
        CP_COMMIT();

        uint32_t aq[2][4][4];
        #pragma unroll
        for (int rb = 0; rb < 2; rb++) {
            const float* q0 = Q + base + (size_t)(rbase + rb * 16 + g) * DH;
            const float* q1 = q0 + 8 * DH;
            #pragma unroll
            for (int kb = 0; kb < 4; kb++) {
                float2 x0 = *(const float2*)(q0 + kb * 16 + 2 * j);
                float2 x1 = *(const float2*)(q1 + kb * 16 + 2 * j);
                float2 x2 = *(const float2*)(q0 + kb * 16 + 2 * j + 8);
                float2 x3 = *(const float2*)(q1 + kb * 16 + 2 * j + 8);
                aq[rb][kb][0] = h2(x0.x * SC_LOG2E, x0.y * SC_LOG2E);
                aq[rb][kb][1] = h2(x1.x * SC_LOG2E, x1.y * SC_LOG2E);
                aq[rb][kb][2] = h2(x2.x * SC_LOG2E, x2.y * SC_LOG2E);
                aq[rb][kb][3] = h2(x3.x * SC_LOG2E, x3.y * SC_LOG2E);
            }
        }

        float o0[9][4], o1[9][4];
        #pragma unroll
        for (int n = 0; n < 9; n++)
            #pragma unroll
            for (int x = 0; x < 4; x++) { o0[n][x] = 0.f; o1[n][x] = 0.f; }

        uint32_t apA0[8], apA1[8], apB0[8], apB1[8];   // carried P (iter kt-1)

        for (int kt = 0; kt < nkt; kt++) {
            CP_WAIT0();
            __syncthreads();

            if (kt + 1 < nkt) {
                const uint32_t nb = (uint32_t)(((kt + 1) % 3)) * BUFB;
                const __half* Kp = Kh + (size_t)(kt + 1) * BC * DH;
                const __half* Vp = Vh + (size_t)(kt + 1) * BC * DH;
                #pragma unroll
                for (int i = 0; i < 4; i++) {
                    cp16(kds[i] + nb, Kp + ld_e[i]);
                    cp16(vds[i] + nb, Vp + ld_e[i]);
                }
                CP_COMMIT();
            }

            const uint32_t ka = ks0 + (uint32_t)(kt % 3) * BUFB + kmoff;
            const uint32_t vprev = vs0 + (uint32_t)((kt + 2) % 3) * BUFB; // (kt-1)%3
            const bool hasmask = (kt >= 2 * q);

            if (kt >= 1 && kt <= last_w) {
                // fused dense block: MMA2(kt-1) then MMA1(kt), one basic block
                do_mma2(o0, o1, apA0, apA1, apB0, apB1, vprev, vmoff, bsum);
                do_mma1_softmax(aq, apA0, apA1, apB0, apB1, ka,
                                hasmask, kt * 64, rA, rB, j2);
            } else if (kt == 0) {
                do_mma1_softmax(aq, apA0, apA1, apB0, apB1, ka,
                                hasmask, 0, rA, rB, j2);
            } else {   // kt == last_w + 1: MMA2 of last P only
                do_mma2(o0, o1, apA0, apA1, apB0, apB1, vprev, vmoff, bsum);
            }
        }
        // drain: warps whose last MMA1 was the final iteration
        if (last_w == nkt - 1) {
            const uint32_t vlast = vs0 + (uint32_t)((nkt - 1) % 3) * BUFB;
            do_mma2(o0, o1, apA0, apA1, apB0, apB1, vlast, vmoff, bsum);
        }

        // ---- epilogue ----
        const float sA0 = __shfl_sync(0xffffffffu, o0[8][0], lane & 28);
        const float sA1 = __shfl_sync(0xffffffffu, o0[8][2], lane & 28);
        const float sB0 = __shfl_sync(0xffffffffu, o1[8][0], lane & 28);
        const float sB1 = __shfl_sync(0xffffffffu, o1[8][2], lane & 28);
        const float iA0 = 1.0f / sA0, iA1 = 1.0f / sA1;
        const float iB0 = 1.0f / sB0, iB1 = 1.0f / sB1;

        float* oA = O + base + (size_t)(rbase + g) * DH;
        float* oB = oA + 16 * DH;
        #pragma unroll
        for (int nb2 = 0; nb2 < 8; nb2++) {
            int c = nb2 * 8 + 2 * j;
            *(float2*)(oA + c)          = make_float2(o0[nb2][0] * iA0, o0[nb2][1] * iA0);
            *(float2*)(oA + 8 * DH + c) = make_float2(o0[nb2][2] * iA1, o0[nb2][3] * iA1);
            *(float2*)(oB + c)          = make_float2(o1[nb2][0] * iB0, o1[nb2][1] * iB0);
            *(float2*)(oB + 8 * DH + c) = make_float2(o1[nb2][2] * iB1, o1[nb2][3] * iB1);
        }
    }
}

extern "C" void kernel_launch(void* const* d_in, const int* in_sizes, int n_in,
                              void* d_out, int out_size)
{
    const float* Q = (const float*)d_in[0];
    const float* K = (const float*)d_in[1];
    const float* V = (const float*)d_in[2];
    float* O = (float*)d_out;

    convKV<<<(int)(KV_ELEMS / 4 / 256), 256>>>(K, V);
    cudaFuncSetAttribute(attn_f16, cudaFuncAttributeMaxDynamicSharedMemorySize,
                         SMEM_BYTES);
    attn_f16<<<NCTA, NT, SMEM_BYTES>>>(Q, O);
}

// round 13
// speedup vs baseline: 1.0631x; 1.0631x over previous
#include <cuda_runtime.h>
#include <cuda_fp16.h>
#include <cstdint>

// Causal attention B=2,H=16,S=2048,D=64 fp32. fp16 mma.sync m16n8k16.
// R13: two k-tiles per sync stage (128-row double-buffered stages) ->
// half the barriers, 208-HMMA dense blocks. Math order identical to R11.

#define S_LEN 2048
#define DH    64
#define BR    128
#define NT    128
#define NQT   (S_LEN/BR)                 // 16
#define BH_N  32
#define NJOBS (NQT*BH_N)                 // 512
#define NCTA  296                        // 2 per SM
#define KPAD  72
#define ROWB  (KPAD*2)                   // 144 B per smem row
#define TILB  (64*ROWB)                  // 9216 B per 64-row tile
#define STGB  (2*TILB)                   // 18432 B per 128-row stage
#define SMEM_BYTES (2*STGB*2)            // 73728: 2 stages x (K+V)
#define SC_LOG2E 0.1803368801111204f
#define NEGINF __int_as_float(0xff800000)

#define KV_ELEMS ((size_t)BH_N * S_LEN * DH)
__device__ __align__(16) __half g_Kh[KV_ELEMS];
__device__ __align__(16) __half g_Vh[KV_ELEMS];
__device__ int g_job;

__device__ __forceinline__ uint32_t smem_u32(const void* p){
    uint32_t a;
    asm("{ .reg .u64 t; cvta.to.shared.u64 t, %1; cvt.u32.u64 %0, t; }" : "=r"(a) : "l"(p));
    return a;
}
__device__ __forceinline__ uint32_t h2(float a, float b){
    __half2 v = __floats2half2_rn(a, b);
    return *reinterpret_cast<uint32_t*>(&v);
}
__device__ __forceinline__ uint32_t ex2h2(uint32_t x){
    uint32_t y; asm("ex2.approx.f16x2 %0, %1;" : "=r"(y) : "r"(x)); return y;
}
__device__ __forceinline__ void ldm_x4(uint32_t r[4], uint32_t addr){
    asm volatile("ldmatrix.sync.aligned.m8n8.x4.shared.b16 {%0,%1,%2,%3}, [%4];"
                 : "=r"(r[0]), "=r"(r[1]), "=r"(r[2]), "=r"(r[3]) : "r"(addr));
}
__device__ __forceinline__ void ldm_x4_t(uint32_t r[4], uint32_t addr){
    asm volatile("ldmatrix.sync.aligned.m8n8.x4.trans.shared.b16 {%0,%1,%2,%3}, [%4];"
                 : "=r"(r[0]), "=r"(r[1]), "=r"(r[2]), "=r"(r[3]) : "r"(addr));
}
__device__ __forceinline__ void mma_f16(float d[4], const uint32_t a[4],
                                        const uint32_t b[2]){
    asm volatile(
        "mma.sync.aligned.m16n8k16.row.col.f32.f16.f16.f32 "
        "{%0,%1,%2,%3}, {%4,%5,%6,%7}, {%8,%9}, {%0,%1,%2,%3};"
        : "+f"(d[0]), "+f"(d[1]), "+f"(d[2]), "+f"(d[3])
        : "r"(a[0]), "r"(a[1]), "r"(a[2]), "r"(a[3]),
          "r"(b[0]), "r"(b[1]));
}
__device__ __forceinline__ void cp16(uint32_t dst, const void* src){
    asm volatile("cp.async.cg.shared.global [%0], [%1], 16;" :: "r"(dst), "l"(src));
}
#define CP_COMMIT() asm volatile("cp.async.commit_group;")
#define CP_WAIT0()  asm volatile("cp.async.wait_group 0;")

__global__ void __launch_bounds__(256) convKV(const float* __restrict__ K,
                                              const float* __restrict__ V){
    if (blockIdx.x == 0 && threadIdx.x == 0) g_job = 0;
    size_t i = ((size_t)blockIdx.x * 256 + threadIdx.x) * 8;
    #pragma unroll
    for (int u = 0; u < 2; u++) {
        float4 k = *reinterpret_cast<const float4*>(K + i + 4 * u);
        float4 v = *reinterpret_cast<const float4*>(V + i + 4 * u);
        uint2 ku; ku.x = h2(k.x, k.y); ku.y = h2(k.z, k.w);
        uint2 vu; vu.x = h2(v.x, v.y); vu.y = h2(v.z, v.w);
        *reinterpret_cast<uint2*>(&g_Kh[i + 4 * u]) = ku;
        *reinterpret_cast<uint2*>(&g_Vh[i + 4 * u]) = vu;
    }
}

// MMA2 over one 64-row V sub-tile (4 indep chain pairs + tensor row-sums)
__device__ __forceinline__ void do_mma2(
    float o0[9][4], float o1[9][4],
    const uint32_t apA0[8], const uint32_t apA1[8],
    const uint32_t apB0[8], const uint32_t apB1[8],
    uint32_t vb, uint32_t vmoff, const uint32_t bsum[2])
{
    #pragma unroll
    for (int np = 0; np < 4; np++) {
        uint32_t bv0[8], bv1[8];
        uint32_t a0 = vb + vmoff + (uint32_t)((2 * np) * 16);
        ldm_x4_t(bv0,     a0);
        ldm_x4_t(bv0 + 4, a0 + 32 * ROWB);
        ldm_x4_t(bv1,     a0 + 16);
        ldm_x4_t(bv1 + 4, a0 + 16 + 32 * ROWB);
        #pragma unroll
        for (int kb = 0; kb < 4; kb++) {
            uint32_t A0[4] = {apA0[2*kb], apA1[2*kb], apA0[2*kb+1], apA1[2*kb+1]};
            uint32_t A1[4] = {apB0[2*kb], apB1[2*kb], apB0[2*kb+1], apB1[2*kb+1]};
            mma_f16(o0[2*np],     A0, bv0 + 2*kb);
            mma_f16(o1[2*np],     A1, bv0 + 2*kb);
            mma_f16(o0[2*np + 1], A0, bv1 + 2*kb);
            mma_f16(o1[2*np + 1], A1, bv1 + 2*kb);
        }
    }
    #pragma unroll
    for (int kb = 0; kb < 4; kb++) {
        uint32_t A0[4] = {apA0[2*kb], apA1[2*kb], apA0[2*kb+1], apA1[2*kb+1]};
        uint32_t A1[4] = {apB0[2*kb], apB1[2*kb], apB0[2*kb+1], apB1[2*kb+1]};
        mma_f16(o0[8], A0, bsum);
        mma_f16(o1[8], A1, bsum);
    }
}

// MMA1 + softmax over one 64-row K sub-tile -> P fragments
__device__ __forceinline__ void do_mma1_softmax(
    const uint32_t aq[2][4][4],
    uint32_t apA0[8], uint32_t apA1[8], uint32_t apB0[8], uint32_t apB1[8],
    uint32_t ka, bool hasmask, int ktbase, int rA, int rB, int j2)
{
    #pragma unroll
    for (int ntp = 0; ntp < 4; ntp++) {
        const int nt0 = 2 * ntp;
        uint32_t b0[8], b1[8];
        uint32_t a0 = ka + (uint32_t)(nt0 * 8 * ROWB);
        ldm_x4(b0,     a0);
        ldm_x4(b0 + 4, a0 + 64);
        ldm_x4(b1,     a0 + 8 * ROWB);
        ldm_x4(b1 + 4, a0 + 8 * ROWB + 64);
        float sA0[4] = {0,0,0,0}, sB0[4] = {0,0,0,0};
        float sA1[4] = {0,0,0,0}, sB1[4] = {0,0,0,0};
        #pragma unroll
        for (int kb = 0; kb < 4; kb++) {
            mma_f16(sA0, aq[0][kb], b0 + 2*kb);
            mma_f16(sB0, aq[1][kb], b0 + 2*kb);
            mma_f16(sA1, aq[0][kb], b1 + 2*kb);
            mma_f16(sB1, aq[1][kb], b1 + 2*kb);
        }
        #pragma unroll
        for (int u = 0; u < 2; u++) {
            float* sA = u ? sA1 : sA0;
            float* sB = u ? sB1 : sB0;
            if (hasmask) {
                int c0 = ktbase + (nt0 + u) * 8 + j2;
                if (c0     > rA)     sA[0] = NEGINF;
                if (c0 + 1 > rA)     sA[1] = NEGINF;
                if (c0     > rA + 8) sA[2] = NEGINF;
                if (c0 + 1 > rA + 8) sA[3] = NEGINF;
                if (c0     > rB)     sB[0] = NEGINF;
                if (c0 + 1 > rB)     sB[1] = NEGINF;
                if (c0     > rB + 8) sB[2] = NEGINF;
                if (c0 + 1 > rB + 8) sB[3] = NEGINF;
            }
            apA0[nt0 + u] = ex2h2(h2(sA[0], sA[1]));
            apA1[nt0 + u] = ex2h2(h2(sA[2], sA[3]));
            apB0[nt0 + u] = ex2h2(h2(sB[0], sB[1]));
            apB1[nt0 + u] = ex2h2(h2(sB[2], sB[3]));
        }
    }
}

__global__ void __launch_bounds__(NT, 2) attn_f16(
    const float* __restrict__ Q, float* __restrict__ O)
{
    extern __shared__ __align__(16) __half sm[];
    __shared__ int sjob;

    const int t = threadIdx.x, lane = t & 31, w = t >> 5;
    const int g = lane >> 2, j = lane & 3;

    const uint32_t ks0 = smem_u32(sm);             // K stages 0,1
    const uint32_t vs0 = ks0 + 2 * STGB;           // V stages 0,1
    const uint32_t kmoff = (uint32_t)((lane & 7) * ROWB + (lane >> 3) * 16);
    const uint32_t vmoff = (uint32_t)(lane * ROWB);

    // cp.async map: 8 chunks per matrix per thread (128 rows x 8 chunks)
    uint32_t kds[8], vds[8];
    int ld_e[8];
    #pragma unroll
    for (int i = 0; i < 8; i++) {
        int idx = t + i * NT;
        int row = idx >> 3, chb = (idx & 7) * 16;
        kds[i] = ks0 + (uint32_t)(row * ROWB + chb);
        vds[i] = vs0 + (uint32_t)(row * ROWB + chb);
        ld_e[i] = row * DH + (chb >> 1);
    }

    const uint32_t bones = (lane < 4) ? 0x3C003C00u : 0u;
    const uint32_t bsum[2] = {bones, bones};

    while (true) {
        if (t == 0) sjob = atomicAdd(&g_job, 1);
        __syncthreads();
        const int job = sjob;
        if (job >= NJOBS) break;
        const int q  = (NQT - 1) - (job >> 5);
        const int bh = job & 31;
        const int nit = q + 1;                      // stages of 2 tiles
        const size_t base = (size_t)bh * S_LEN * DH;
        const __half* Kh = g_Kh + base;
        const __half* Vh = g_Vh + base;
        const int rbase = q * BR + w * 32;
        const int wrow_max = rbase + 31;
        const int rA = rbase + g, rB = rA + 16, j2 = 2 * j;

        // stage 0 loads
        #pragma unroll
        for (int i = 0; i < 8; i++) {
            cp16(kds[i], Kh + ld_e[i]);
            cp16(vds[i], Vh + ld_e[i]);
        }
        CP_COMMIT();

        // Q -> fp16 A-fragments, pre-scaled
        uint32_t aq[2][4][4];
        #pragma unroll
        for (int rb = 0; rb < 2; rb++) {
            const float* q0 = Q + base + (size_t)(rbase + rb * 16 + g) * DH;
            const float* q1 = q0 + 8 * DH;
            #pragma unroll
            for (int kb = 0; kb < 4; kb++) {
                float2 x0 = *(const float2*)(q0 + kb * 16 + 2 * j);
                float2 x1 = *(const float2*)(q1 + kb * 16 + 2 * j);
                float2 x2 = *(const float2*)(q0 + kb * 16 + 2 * j + 8);
                float2 x3 = *(const float2*)(q1 + kb * 16 + 2 * j + 8);
                aq[rb][kb][0] = h2(x0.x * SC_LOG2E, x0.y * SC_LOG2E);
                aq[rb][kb][1] = h2(x1.x * SC_LOG2E, x1.y * SC_LOG2E);
                aq[rb][kb][2] = h2(x2.x * SC_LOG2E, x2.y * SC_LOG2E);
                aq[rb][kb][3] = h2(x3.x * SC_LOG2E, x3.y * SC_LOG2E);
            }
        }

        float o0[9][4], o1[9][4];
        #pragma unroll
        for (int n = 0; n < 9; n++)
            #pragma unroll
            for (int x = 0; x < 4; x++) { o0[n][x] = 0.f; o1[n][x] = 0.f; }

        for (int it = 0; it < nit; it++) {
            CP_WAIT0();                 // my stage-it chunks complete
            __syncthreads();            // publish all; WAR-safe other stage

            if (it + 1 < nit) {         // prefetch stage it+1
                const uint32_t nb = (uint32_t)(((it + 1) & 1)) * STGB;
                const __half* Kp = Kh + (size_t)(it + 1) * 128 * DH;
                const __half* Vp = Vh + (size_t)(it + 1) * 128 * DH;
                #pragma unroll
                for (int i = 0; i < 8; i++) {
                    cp16(kds[i] + nb, Kp + ld_e[i]);
                    cp16(vds[i] + nb, Vp + ld_e[i]);
                }
                CP_COMMIT();
            }

            const uint32_t kstage = ks0 + (uint32_t)(it & 1) * STGB;
            const uint32_t vstage = vs0 + (uint32_t)(it & 1) * STGB;
            const bool hasmask = (it == q);
            uint32_t apA0[8], apA1[8], apB0[8], apB1[8];

            // ---- sub-tile 0 (kt = 2it) ----
            {
                do_mma1_softmax(aq, apA0, apA1, apB0, apB1,
                                kstage + kmoff, hasmask, 2 * it * 64,
                                rA, rB, j2);
                do_mma2(o0, o1, apA0, apA1, apB0, apB1,
                        vstage, vmoff, bsum);
            }
            // ---- sub-tile 1 (kt = 2it+1) ----
            if ((2 * it + 1) * 64 <= wrow_max) {
                do_mma1_softmax(aq, apA0, apA1, apB0, apB1,
                                kstage + TILB + kmoff, hasmask,
                                (2 * it + 1) * 64, rA, rB, j2);
                do_mma2(o0, o1, apA0, apA1, apB0, apB1,
                        vstage + TILB, vmoff, bsum);
            }
        }

        // ---- epilogue ----
        const float sA0 = __shfl_sync(0xffffffffu, o0[8][0], lane & 28);
        const float sA1 = __shfl_sync(0xffffffffu, o0[8][2], lane & 28);
        const float sB0 = __shfl_sync(0xffffffffu, o1[8][0], lane & 28);
        const float sB1 = __shfl_sync(0xffffffffu, o1[8][2], lane & 28);
        const float iA0 = 1.0f / sA0, iA1 = 1.0f / sA1;
        const float iB0 = 1.0f / sB0, iB1 = 1.0f / sB1;

        float* oA = O + base + (size_t)(rbase + g) * DH;
        float* oB = oA + 16 * DH;
        #pragma unroll
        for (int nb2 = 0; nb2 < 8; nb2++) {
            int c = nb2 * 8 + 2 * j;
            *(float2*)(oA + c)          = make_float2(o0[nb2][0] * iA0, o0[nb2][1] * iA0);
            *(float2*)(oA + 8 * DH + c) = make_float2(o0[nb2][2] * iA1, o0[nb2][3] * iA1);
            *(float2*)(oB + c)          = make_float2(o1[nb2][0] * iB0, o1[nb2][1] * iB0);
            *(float2*)(oB + 8 * DH + c) = make_float2(o1[nb2][2] * iB1, o1[nb2][3] * iB1);
        }
    }
}

extern "C" void kernel_launch(void* const* d_in, const int* in_sizes, int n_in,
                              void* d_out, int out_size)
{
    const float* Q = (const float*)d_in[0];
    const float* K = (const float*)d_in[1];
    const float* V = (const float*)d_in[2];
    float* O = (float*)d_out;

    convKV<<<(int)(KV_ELEMS / 8 / 256), 256>>>(K, V);
    cudaFuncSetAttribute(attn_f16, cudaFuncAttributeMaxDynamicSharedMemorySize,
                         SMEM_BYTES);
    attn_f16<<<NCTA, NT, SMEM_BYTES>>>(Q, O);
}